// round 16
// baseline (speedup 1.0000x reference)
#include <cuda_runtime.h>
#include <stdint.h>

// Problem constants
#define NPTS   512          // number of nodes (rows of x)
#define NIN    256          // input feature dim
#define NOUT   256          // output feature dim
#define NCOMB  512          // combined projection width: [A' | B]

// Scratch: O[i][o'] ; o'<256 -> A'[i][o'] (bias folded), o'>=256 -> B[i][o'-256].
__device__ float g_O[NPTS * NCOMB];   // 1 MB (L2-resident during the fill)

// ---- packed f32x2 helpers (sm_103a; ptxas never auto-fuses these) ----------
__device__ __forceinline__ void fma_f32x2(unsigned long long& acc,
                                          unsigned long long a,
                                          unsigned long long b) {
    asm("fma.rn.f32x2 %0, %1, %2, %0;" : "+l"(acc) : "l"(a), "l"(b));
}
__device__ __forceinline__ unsigned long long pack2(float lo, float hi) {
    unsigned long long r;
    asm("mov.b64 %0, {%1, %2};" : "=l"(r) : "f"(lo), "f"(hi));
    return r;
}
__device__ __forceinline__ void unpack2(float& lo, float& hi, unsigned long long v) {
    asm("mov.b64 {%0, %1}, %2;" : "=f"(lo), "=f"(hi) : "l"(v));
}

// ---------------------------------------------------------------------------
// Kernel 1: O = X @ V,  V[k][o'] = W[o'][k] (o'<256) or W[o'-256][256+k].
// R13 structure (the measured-best): 64 rows x 32 cols tiles -> 128 CTAs,
// K panels of 32, double-buffered smem pipeline, 4x2 micro-tile.
// NEW: inner product uses fma.rn.f32x2 — row pairs come packed for free out
// of the LDS.128, B columns broadcast as packed pairs -> FMA issues halved.
// ---------------------------------------------------------------------------
#define GK    32
#define NPAN  (NIN / GK)      // 8 panels
#define XPAD  68              // 64 rows + pad (16B-aligned pitch)
#define VPAD  34              // 32 cols + pad (8B-aligned pitch)

__global__ __launch_bounds__(256) void proj_gemm_kernel(
    const float* __restrict__ X,   // [512, 256]
    const float* __restrict__ W,   // [256, 512]
    const float* __restrict__ bias // [256]
) {
    __shared__ float Xs[2][GK][XPAD];
    __shared__ float Vs[2][GK][VPAD];

    const int tx  = threadIdx.x;           // 0..15 -> col pair 2*tx
    const int ty  = threadIdx.y;           // 0..15 -> row quad 4*ty
    const int tid = ty * 16 + tx;
    const int o0  = blockIdx.x * 32;       // col tile origin (combined width)
    const int r0  = blockIdx.y * 64;       // row tile origin

    // Per-thread global sources (advance by GK each panel).
    const int xr0 = tid >> 3;               // 0..31
    const int xkk = (tid & 7) << 2;         // 0,4,..,28
    const float* xsrc0 = &X[(r0 + xr0)      * NIN + xkk];
    const float* xsrc1 = &X[(r0 + xr0 + 32) * NIN + xkk];
    const int voo = tid >> 3;               // 0..31
    const int o   = o0 + voo;
    const float* vsrc = (o < NOUT) ? &W[o * (2 * NIN) + xkk]
                                   : &W[(o - NOUT) * (2 * NIN) + NIN + xkk];

    // Packed accumulators: acc[rp][c] = {row(2rp) , row(2rp+1)} for column c.
    unsigned long long acc00 = 0ull, acc01 = 0ull, acc10 = 0ull, acc11 = 0ull;

    // Preload panel 0 into buffer 0.
    {
        float4 x0 = *(const float4*)xsrc0;
        float4 x1 = *(const float4*)xsrc1;
        float4 v  = *(const float4*)vsrc;
        Xs[0][xkk+0][xr0]    = x0.x; Xs[0][xkk+1][xr0]    = x0.y;
        Xs[0][xkk+2][xr0]    = x0.z; Xs[0][xkk+3][xr0]    = x0.w;
        Xs[0][xkk+0][xr0+32] = x1.x; Xs[0][xkk+1][xr0+32] = x1.y;
        Xs[0][xkk+2][xr0+32] = x1.z; Xs[0][xkk+3][xr0+32] = x1.w;
        Vs[0][xkk+0][voo] = v.x; Vs[0][xkk+1][voo] = v.y;
        Vs[0][xkk+2][voo] = v.z; Vs[0][xkk+3][voo] = v.w;
    }
    __syncthreads();

#pragma unroll
    for (int p = 0; p < NPAN; p++) {
        const int buf = p & 1;
        float4 nx0, nx1, nv;
        if (p + 1 < NPAN) {
            nx0 = *(const float4*)(xsrc0 + (p + 1) * GK);
            nx1 = *(const float4*)(xsrc1 + (p + 1) * GK);
            nv  = *(const float4*)(vsrc  + (p + 1) * GK);
        }
#pragma unroll
        for (int kk = 0; kk < GK; kk++) {
            float4 xr = *(const float4*)&Xs[buf][kk][4 * ty];  // 4 rows, LDS.128
            float2 vo = *(const float2*)&Vs[buf][kk][2 * tx];  // 2 cols, LDS.64
            // Row pairs are adjacent registers out of the LDS.128 -> packs are free.
            unsigned long long xp0 = pack2(xr.x, xr.y);
            unsigned long long xp1 = pack2(xr.z, xr.w);
            unsigned long long v0  = pack2(vo.x, vo.x);  // broadcast col0
            unsigned long long v1  = pack2(vo.y, vo.y);  // broadcast col1
            fma_f32x2(acc00, xp0, v0);
            fma_f32x2(acc01, xp0, v1);
            fma_f32x2(acc10, xp1, v0);
            fma_f32x2(acc11, xp1, v1);
        }
        if (p + 1 < NPAN) {
            const int nb = buf ^ 1;
            Xs[nb][xkk+0][xr0]    = nx0.x; Xs[nb][xkk+1][xr0]    = nx0.y;
            Xs[nb][xkk+2][xr0]    = nx0.z; Xs[nb][xkk+3][xr0]    = nx0.w;
            Xs[nb][xkk+0][xr0+32] = nx1.x; Xs[nb][xkk+1][xr0+32] = nx1.y;
            Xs[nb][xkk+2][xr0+32] = nx1.z; Xs[nb][xkk+3][xr0+32] = nx1.w;
            Vs[nb][xkk+0][voo] = nv.x; Vs[nb][xkk+1][voo] = nv.y;
            Vs[nb][xkk+2][voo] = nv.z; Vs[nb][xkk+3][voo] = nv.w;
        }
        __syncthreads();
    }

    // Unpack + store as float2 rows, folding bias into the A' half (o < 256).
    const int oA = o0 + 2 * tx;
    const float biasA = (oA     < NOUT) ? bias[oA]     : 0.0f;
    const float biasB = (oA + 1 < NOUT) ? bias[oA + 1] : 0.0f;
    {
        float r0c0, r1c0, r2c0, r3c0, r0c1, r1c1, r2c1, r3c1;
        unpack2(r0c0, r1c0, acc00);
        unpack2(r0c1, r1c1, acc01);
        unpack2(r2c0, r3c0, acc10);
        unpack2(r2c1, r3c1, acc11);
        const int r = r0 + 4 * ty;
        *(float2*)&g_O[(uint32_t)(r + 0) * NCOMB + oA] = make_float2(r0c0 + biasA, r0c1 + biasB);
        *(float2*)&g_O[(uint32_t)(r + 1) * NCOMB + oA] = make_float2(r1c0 + biasA, r1c1 + biasB);
        *(float2*)&g_O[(uint32_t)(r + 2) * NCOMB + oA] = make_float2(r2c0 + biasA, r2c1 + biasB);
        *(float2*)&g_O[(uint32_t)(r + 3) * NCOMB + oA] = make_float2(r3c0 + biasA, r3c1 + biasB);
    }
}

// ---------------------------------------------------------------------------
// Kernel 2: out[i][j][:] = A'[min(i,j)] + B[max(i,j)], 0 on diagonal.
// Packed triangular grid (2080 CTAs), symmetric double-store float4 __stcs —
// the measured-best store pattern (40.5us @ DRAM 65.4%). Unchanged from R14.
// ---------------------------------------------------------------------------
__global__ __launch_bounds__(256) void pairwise_fill_kernel(float4* __restrict__ out) {
    // Decode linear tile index k -> (ti, tj) with ti <= tj < 64.
    const int k = blockIdx.x;
    float f = sqrtf(16641.0f - 8.0f * (float)k);       // 129^2 = 16641
    int ti = (int)((129.0f - f) * 0.5f);
    while ((ti + 1) * (129 - (ti + 1)) / 2 <= k) ti++;
    while (ti * (129 - ti) / 2 > k) ti--;
    const int tj = ti + (k - ti * (129 - ti) / 2);

    const int c4   = threadIdx.x & 63;      // 0..63 : channel/4
    const int rsel = threadIdx.x >> 6;      // 0..3
    const float4* __restrict__ O4 = (const float4*)g_O;  // rows of 128 float4

    float4 a[2], b[8];
#pragma unroll
    for (int u = 0; u < 2; u++)
        a[u] = O4[(uint32_t)(ti * 8 + 2 * rsel + u) * 128 + c4];
#pragma unroll
    for (int jj = 0; jj < 8; jj++)
        b[jj] = O4[(uint32_t)(tj * 8 + jj) * 128 + 64 + c4];

    if (ti != tj) {
#pragma unroll
        for (int u = 0; u < 2; u++) {
            const int i = ti * 8 + 2 * rsel + u;
#pragma unroll
            for (int jj = 0; jj < 8; jj++) {
                const int j = tj * 8 + jj;
                float4 v;
                v.x = a[u].x + b[jj].x;
                v.y = a[u].y + b[jj].y;
                v.z = a[u].z + b[jj].z;
                v.w = a[u].w + b[jj].w;
                __stcs(&out[((uint32_t)i * NPTS + j) * 64 + c4], v);
                __stcs(&out[((uint32_t)j * NPTS + i) * 64 + c4], v);
            }
        }
    } else {
#pragma unroll
        for (int u = 0; u < 2; u++) {
            const int li = 2 * rsel + u;
            const int i  = ti * 8 + li;
#pragma unroll
            for (int jj = 0; jj < 8; jj++) {
                const int j = tj * 8 + jj;
                if (li < jj) {
                    float4 v;
                    v.x = a[u].x + b[jj].x;
                    v.y = a[u].y + b[jj].y;
                    v.z = a[u].z + b[jj].z;
                    v.w = a[u].w + b[jj].w;
                    __stcs(&out[((uint32_t)i * NPTS + j) * 64 + c4], v);
                    __stcs(&out[((uint32_t)j * NPTS + i) * 64 + c4], v);
                } else if (li == jj) {
                    float4 z = make_float4(0.f, 0.f, 0.f, 0.f);
                    __stcs(&out[((uint32_t)i * NPTS + j) * 64 + c4], z);
                }
            }
        }
    }
}

// ---------------------------------------------------------------------------
// Launch
// ---------------------------------------------------------------------------
extern "C" void kernel_launch(void* const* d_in, const int* in_sizes, int n_in,
                              void* d_out, int out_size) {
    const float* x = (const float*)d_in[0];   // [512, 256]
    const float* W = (const float*)d_in[1];   // [256, 512]
    const float* b = (const float*)d_in[2];   // [256]
    float4* out = (float4*)d_out;             // [512, 512, 256] fp32

    (void)in_sizes; (void)n_in; (void)out_size;

    // 1) Pre-projection: 128 CTAs, double-buffered, packed f32x2 FMAs.
    {
        dim3 grid(NCOMB / 32, NPTS / 64);   // (16, 8)
        dim3 block(16, 16);
        proj_gemm_kernel<<<grid, block>>>(x, W, b);
    }
    // 2) Broadcast-add fill: packed upper-triangular grid, symmetric writes.
    {
        const int ntiles = (NPTS / 8) * (NPTS / 8 + 1) / 2;  // 2080
        pairwise_fill_kernel<<<ntiles, 256>>>(out);
    }
}

// round 17
// speedup vs baseline: 1.0050x; 1.0050x over previous
#include <cuda_runtime.h>
#include <stdint.h>

// Problem constants
#define NPTS   512          // number of nodes (rows of x)
#define NIN    256          // input feature dim
#define NOUT   256          // output feature dim
#define NCOMB  512          // combined projection width: [A' | B]

// Scratch: O[i][o'] ; o'<256 -> A'[i][o'] (bias folded), o'>=256 -> B[i][o'-256].
__device__ float g_O[NPTS * NCOMB];   // 1 MB (L2-resident during the fill)

// ---- packed f32x2 helpers (sm_103a; ptxas never auto-fuses these) ----------
__device__ __forceinline__ void fma_f32x2(unsigned long long& acc,
                                          unsigned long long a,
                                          unsigned long long b) {
    asm("fma.rn.f32x2 %0, %1, %2, %0;" : "+l"(acc) : "l"(a), "l"(b));
}
__device__ __forceinline__ unsigned long long pack2(float lo, float hi) {
    unsigned long long r;
    asm("mov.b64 %0, {%1, %2};" : "=l"(r) : "f"(lo), "f"(hi));
    return r;
}
__device__ __forceinline__ void unpack2(float& lo, float& hi, unsigned long long v) {
    asm("mov.b64 {%0, %1}, %2;" : "=f"(lo), "=f"(hi) : "l"(v));
}

// ---------------------------------------------------------------------------
// Kernel 1: O = X @ V,  V[k][o'] = W[o'][k] (o'<256) or W[o'-256][256+k].
// R13 structure (the measured-best): 64 rows x 32 cols tiles -> 128 CTAs,
// K panels of 32, double-buffered smem pipeline, 4x2 micro-tile.
// NEW: inner product uses fma.rn.f32x2 — row pairs come packed for free out
// of the LDS.128, B columns broadcast as packed pairs -> FMA issues halved.
// ---------------------------------------------------------------------------
#define GK    32
#define NPAN  (NIN / GK)      // 8 panels
#define XPAD  68              // 64 rows + pad (16B-aligned pitch)
#define VPAD  34              // 32 cols + pad (8B-aligned pitch)

__global__ __launch_bounds__(256) void proj_gemm_kernel(
    const float* __restrict__ X,   // [512, 256]
    const float* __restrict__ W,   // [256, 512]
    const float* __restrict__ bias // [256]
) {
    __shared__ float Xs[2][GK][XPAD];
    __shared__ float Vs[2][GK][VPAD];

    const int tx  = threadIdx.x;           // 0..15 -> col pair 2*tx
    const int ty  = threadIdx.y;           // 0..15 -> row quad 4*ty
    const int tid = ty * 16 + tx;
    const int o0  = blockIdx.x * 32;       // col tile origin (combined width)
    const int r0  = blockIdx.y * 64;       // row tile origin

    // Per-thread global sources (advance by GK each panel).
    const int xr0 = tid >> 3;               // 0..31
    const int xkk = (tid & 7) << 2;         // 0,4,..,28
    const float* xsrc0 = &X[(r0 + xr0)      * NIN + xkk];
    const float* xsrc1 = &X[(r0 + xr0 + 32) * NIN + xkk];
    const int voo = tid >> 3;               // 0..31
    const int o   = o0 + voo;
    const float* vsrc = (o < NOUT) ? &W[o * (2 * NIN) + xkk]
                                   : &W[(o - NOUT) * (2 * NIN) + NIN + xkk];

    // Packed accumulators: acc[rp][c] = {row(2rp) , row(2rp+1)} for column c.
    unsigned long long acc00 = 0ull, acc01 = 0ull, acc10 = 0ull, acc11 = 0ull;

    // Preload panel 0 into buffer 0.
    {
        float4 x0 = *(const float4*)xsrc0;
        float4 x1 = *(const float4*)xsrc1;
        float4 v  = *(const float4*)vsrc;
        Xs[0][xkk+0][xr0]    = x0.x; Xs[0][xkk+1][xr0]    = x0.y;
        Xs[0][xkk+2][xr0]    = x0.z; Xs[0][xkk+3][xr0]    = x0.w;
        Xs[0][xkk+0][xr0+32] = x1.x; Xs[0][xkk+1][xr0+32] = x1.y;
        Xs[0][xkk+2][xr0+32] = x1.z; Xs[0][xkk+3][xr0+32] = x1.w;
        Vs[0][xkk+0][voo] = v.x; Vs[0][xkk+1][voo] = v.y;
        Vs[0][xkk+2][voo] = v.z; Vs[0][xkk+3][voo] = v.w;
    }
    __syncthreads();

#pragma unroll
    for (int p = 0; p < NPAN; p++) {
        const int buf = p & 1;
        float4 nx0, nx1, nv;
        if (p + 1 < NPAN) {
            nx0 = *(const float4*)(xsrc0 + (p + 1) * GK);
            nx1 = *(const float4*)(xsrc1 + (p + 1) * GK);
            nv  = *(const float4*)(vsrc  + (p + 1) * GK);
        }
#pragma unroll
        for (int kk = 0; kk < GK; kk++) {
            float4 xr = *(const float4*)&Xs[buf][kk][4 * ty];  // 4 rows, LDS.128
            float2 vo = *(const float2*)&Vs[buf][kk][2 * tx];  // 2 cols, LDS.64
            // Row pairs are adjacent registers out of the LDS.128 -> packs are free.
            unsigned long long xp0 = pack2(xr.x, xr.y);
            unsigned long long xp1 = pack2(xr.z, xr.w);
            unsigned long long v0  = pack2(vo.x, vo.x);  // broadcast col0
            unsigned long long v1  = pack2(vo.y, vo.y);  // broadcast col1
            fma_f32x2(acc00, xp0, v0);
            fma_f32x2(acc01, xp0, v1);
            fma_f32x2(acc10, xp1, v0);
            fma_f32x2(acc11, xp1, v1);
        }
        if (p + 1 < NPAN) {
            const int nb = buf ^ 1;
            Xs[nb][xkk+0][xr0]    = nx0.x; Xs[nb][xkk+1][xr0]    = nx0.y;
            Xs[nb][xkk+2][xr0]    = nx0.z; Xs[nb][xkk+3][xr0]    = nx0.w;
            Xs[nb][xkk+0][xr0+32] = nx1.x; Xs[nb][xkk+1][xr0+32] = nx1.y;
            Xs[nb][xkk+2][xr0+32] = nx1.z; Xs[nb][xkk+3][xr0+32] = nx1.w;
            Vs[nb][xkk+0][voo] = nv.x; Vs[nb][xkk+1][voo] = nv.y;
            Vs[nb][xkk+2][voo] = nv.z; Vs[nb][xkk+3][voo] = nv.w;
        }
        __syncthreads();
    }

    // Unpack + store as float2 rows, folding bias into the A' half (o < 256).
    const int oA = o0 + 2 * tx;
    const float biasA = (oA     < NOUT) ? bias[oA]     : 0.0f;
    const float biasB = (oA + 1 < NOUT) ? bias[oA + 1] : 0.0f;
    {
        float r0c0, r1c0, r2c0, r3c0, r0c1, r1c1, r2c1, r3c1;
        unpack2(r0c0, r1c0, acc00);
        unpack2(r0c1, r1c1, acc01);
        unpack2(r2c0, r3c0, acc10);
        unpack2(r2c1, r3c1, acc11);
        const int r = r0 + 4 * ty;
        *(float2*)&g_O[(uint32_t)(r + 0) * NCOMB + oA] = make_float2(r0c0 + biasA, r0c1 + biasB);
        *(float2*)&g_O[(uint32_t)(r + 1) * NCOMB + oA] = make_float2(r1c0 + biasA, r1c1 + biasB);
        *(float2*)&g_O[(uint32_t)(r + 2) * NCOMB + oA] = make_float2(r2c0 + biasA, r2c1 + biasB);
        *(float2*)&g_O[(uint32_t)(r + 3) * NCOMB + oA] = make_float2(r3c0 + biasA, r3c1 + biasB);
    }
}

// ---------------------------------------------------------------------------
// Kernel 2: out[i][j][:] = A'[min(i,j)] + B[max(i,j)], 0 on diagonal.
// Packed triangular grid (2080 CTAs), symmetric double-store float4 __stcs —
// the measured-best store pattern (40.5us @ DRAM 65.4%). Unchanged from R14.
// ---------------------------------------------------------------------------
__global__ __launch_bounds__(256) void pairwise_fill_kernel(float4* __restrict__ out) {
    // Decode linear tile index k -> (ti, tj) with ti <= tj < 64.
    const int k = blockIdx.x;
    float f = sqrtf(16641.0f - 8.0f * (float)k);       // 129^2 = 16641
    int ti = (int)((129.0f - f) * 0.5f);
    while ((ti + 1) * (129 - (ti + 1)) / 2 <= k) ti++;
    while (ti * (129 - ti) / 2 > k) ti--;
    const int tj = ti + (k - ti * (129 - ti) / 2);

    const int c4   = threadIdx.x & 63;      // 0..63 : channel/4
    const int rsel = threadIdx.x >> 6;      // 0..3
    const float4* __restrict__ O4 = (const float4*)g_O;  // rows of 128 float4

    float4 a[2], b[8];
#pragma unroll
    for (int u = 0; u < 2; u++)
        a[u] = O4[(uint32_t)(ti * 8 + 2 * rsel + u) * 128 + c4];
#pragma unroll
    for (int jj = 0; jj < 8; jj++)
        b[jj] = O4[(uint32_t)(tj * 8 + jj) * 128 + 64 + c4];

    if (ti != tj) {
#pragma unroll
        for (int u = 0; u < 2; u++) {
            const int i = ti * 8 + 2 * rsel + u;
#pragma unroll
            for (int jj = 0; jj < 8; jj++) {
                const int j = tj * 8 + jj;
                float4 v;
                v.x = a[u].x + b[jj].x;
                v.y = a[u].y + b[jj].y;
                v.z = a[u].z + b[jj].z;
                v.w = a[u].w + b[jj].w;
                __stcs(&out[((uint32_t)i * NPTS + j) * 64 + c4], v);
                __stcs(&out[((uint32_t)j * NPTS + i) * 64 + c4], v);
            }
        }
    } else {
#pragma unroll
        for (int u = 0; u < 2; u++) {
            const int li = 2 * rsel + u;
            const int i  = ti * 8 + li;
#pragma unroll
            for (int jj = 0; jj < 8; jj++) {
                const int j = tj * 8 + jj;
                if (li < jj) {
                    float4 v;
                    v.x = a[u].x + b[jj].x;
                    v.y = a[u].y + b[jj].y;
                    v.z = a[u].z + b[jj].z;
                    v.w = a[u].w + b[jj].w;
                    __stcs(&out[((uint32_t)i * NPTS + j) * 64 + c4], v);
                    __stcs(&out[((uint32_t)j * NPTS + i) * 64 + c4], v);
                } else if (li == jj) {
                    float4 z = make_float4(0.f, 0.f, 0.f, 0.f);
                    __stcs(&out[((uint32_t)i * NPTS + j) * 64 + c4], z);
                }
            }
        }
    }
}

// ---------------------------------------------------------------------------
// Launch
// ---------------------------------------------------------------------------
extern "C" void kernel_launch(void* const* d_in, const int* in_sizes, int n_in,
                              void* d_out, int out_size) {
    const float* x = (const float*)d_in[0];   // [512, 256]
    const float* W = (const float*)d_in[1];   // [256, 512]
    const float* b = (const float*)d_in[2];   // [256]
    float4* out = (float4*)d_out;             // [512, 512, 256] fp32

    (void)in_sizes; (void)n_in; (void)out_size;

    // 1) Pre-projection: 128 CTAs, double-buffered, packed f32x2 FMAs.
    {
        dim3 grid(NCOMB / 32, NPTS / 64);   // (16, 8)
        dim3 block(16, 16);
        proj_gemm_kernel<<<grid, block>>>(x, W, b);
    }
    // 2) Broadcast-add fill: packed upper-triangular grid, symmetric writes.
    {
        const int ntiles = (NPTS / 8) * (NPTS / 8 + 1) / 2;  // 2080
        pairwise_fill_kernel<<<ntiles, 256>>>(out);
    }
}